// round 12
// baseline (speedup 1.0000x reference)
#include <cuda_runtime.h>
#include <cstdint>

#define BATCH    64
#define SEQ      8192
#define RDIM     80
#define RING     169
#define RINGF    (RING * RDIM)        // 13520 floats
#define NTHREADS 448                  // 14 warps
#define NSUPER   (SEQ / 4)            // 2048 supersteps
#define BUFBANK  1280                 // floats per partial bank: 4 steps * 80 * 4

typedef unsigned long long u64;

__device__ __forceinline__ u64 ffma2(u64 a, u64 b, u64 c) {
    u64 d;
    asm("fma.rn.f32x2 %0, %1, %2, %3;" : "=l"(d) : "l"(a), "l"(b), "l"(c));
    return d;
}
__device__ __forceinline__ u64 fadd2(u64 a, u64 b) {
    u64 d;
    asm("add.rn.f32x2 %0, %1, %2;" : "=l"(d) : "l"(a), "l"(b));
    return d;
}
__device__ __forceinline__ float2 unpack2(u64 v) {
    unsigned lo, hi;
    asm("mov.b64 {%0, %1}, %2;" : "=r"(lo), "=r"(hi) : "l"(v));
    float2 r; r.x = __uint_as_float(lo); r.y = __uint_as_float(hi);
    return r;
}
__device__ __forceinline__ float fast_tanh(float v) {
    v = fminf(fmaxf(v, -15.0f), 15.0f);
    float u = __expf(-2.0f * v);
    return __fdividef(1.0f - u, 1.0f + u);
}

// Full 80-MAC row: 10x2 LDS.128 (broadcast) + 40 FFMA2 in 4 chains -> scalar
__device__ __forceinline__ float row_dot(const u64* W, const float* hrow) {
    const ulonglong2* hv = reinterpret_cast<const ulonglong2*>(hrow);
    u64 a0 = 0ull, a1 = 0ull, a2 = 0ull, a3 = 0ull;
#pragma unroll
    for (int p = 0; p < 10; p++) {
        ulonglong2 A = hv[2 * p];
        ulonglong2 B = hv[2 * p + 1];
        a0 = ffma2(A.x, W[4 * p + 0], a0);
        a1 = ffma2(A.y, W[4 * p + 1], a1);
        a2 = ffma2(B.x, W[4 * p + 2], a2);
        a3 = ffma2(B.y, W[4 * p + 3], a3);
    }
    float2 r = unpack2(fadd2(fadd2(a0, a1), fadd2(a2, a3)));
    return r.x + r.y;
}

__device__ __forceinline__ void load_wrow(u64* W, const float* wrow) {
#pragma unroll
    for (int p = 0; p < 40; p++) {
        unsigned lo = __float_as_uint(wrow[2 * p]);
        unsigned hi = __float_as_uint(wrow[2 * p + 1]);
        W[p] = ((u64)hi << 32) | (u64)lo;
    }
}

// Named barriers: id1 = consumer-internal (96), id2 = tap4->consumer (192)
#define BAR_CONS()        asm volatile("bar.sync 1, 96;"    ::: "memory")
#define BAR_T4_SYNC()     asm volatile("bar.sync 2, 192;"   ::: "memory")
#define BAR_T4_ARRIVE()   asm volatile("bar.arrive 2, 192;" ::: "memory")

__global__ __launch_bounds__(NTHREADS, 1)
void reservoir_kernel(const float* __restrict__ x,
                      const float* __restrict__ Win,
                      const float* __restrict__ Wfb,
                      const float* __restrict__ bias,
                      float* __restrict__ out)
{
    extern __shared__ float sm[];
    float* Hring = sm;                   // [RING][RDIM]
    float* xs    = Hring + RINGF;        // [SEQ]
    float* buf   = xs + SEQ;             // [2][4][80][4]  partial banks

    const int b   = blockIdx.x;
    const int tid = threadIdx.x;
    const int wid = tid >> 5;

    for (int idx = tid; idx < RINGF; idx += NTHREADS) Hring[idx] = 0.0f;
    for (int idx = tid; idx < 2 * BUFBANK; idx += NTHREADS) buf[idx] = 0.0f;
    const float* xb = x + (size_t)b * SEQ;
    for (int idx = tid; idx < SEQ; idx += NTHREADS) xs[idx] = xb[idx];

    float* outb = out + (size_t)b * SEQ * RDIM;
    const float* const ring_end = Hring + RINGF;

    __syncthreads();

    if (wid >= 11) {
        // ============ CONSUMERS (warps 11-13, highest priority) ============
        const int lane = tid - 352;                 // 0..95
        const bool act = lane < RDIM;
        const int i    = act ? lane : 0;

        u64 W1[40];
        load_wrow(W1, Wfb + (size_t)i * RDIM);      // tau=1 row
        const float win_i  = Win[i];
        const float bias_i = bias[i];
        float h_i = 0.0f;

        const float* hr = Hring + 168 * RDIM;       // h[t-1] row, t=0
        float* hw = Hring + i;                      // write slot 0
        float* op = outb + i;
        int par = 0;

#pragma unroll 1
        for (int n = 0; n < NSUPER; ++n) {
            // step T matvec first: h[T-1] already visible (B0 / bar96 chain)
            float fh = row_dot(W1, hr);
            hr += RDIM; if (hr >= ring_end) hr -= RINGF;

            float4 xv = *reinterpret_cast<const float4*>(xs + 4 * n);

            BAR_T4_SYNC();     // tap4 partials of this superstep published

            const float4* pb = reinterpret_cast<const float4*>(buf + par * BUFBANK);
            float4 P0 = pb[0 * RDIM + i];
            float4 P1 = pb[1 * RDIM + i];
            float4 P2 = pb[2 * RDIM + i];
            float4 P3 = pb[3 * RDIM + i];

#pragma unroll
            for (int s = 0; s < 4; ++s) {
                float4 P  = (s == 0) ? P0 : (s == 1) ? P1 : (s == 2) ? P2 : P3;
                float x_t = (s == 0) ? xv.x : (s == 1) ? xv.y : (s == 2) ? xv.z : xv.w;

                if (s > 0) {
                    fh = row_dot(W1, hr);           // vs h[t-1] (just written)
                    hr += RDIM; if (hr >= ring_end) hr -= RINGF;
                }

                float f   = fh + ((P.x + P.y) + (P.z + P.w));
                float val = fmaf(x_t, win_i, f + bias_i);
                h_i = 0.7f * h_i + 0.3f * fast_tanh(val);

                if (act) { *hw = h_i; *op = h_i; }
                hw += RDIM; if (hw >= ring_end) hw -= RINGF;
                op += RDIM;

                if (s < 3) BAR_CONS();              // publish h within group
            }
            par ^= 1;
            __syncthreads();                        // B0: superstep boundary
        }
    } else if (wid >= 8) {
        // ============ TAP-4 PRODUCERS (warps 8-10) ============
        const int lane = tid - 256;
        const bool act = lane < RDIM;
        const int i    = act ? lane : 0;

        u64 W4[40];
        load_wrow(W4, Wfb + ((size_t)1 * RDIM + i) * RDIM);   // tau=4 row

        const float* hr = Hring + 165 * RDIM;       // h[t-4] for t=0
        int par = 0;

#pragma unroll 1
        for (int n = 0; n < NSUPER; ++n) {
            float* pw = buf + par * BUFBANK + i * 4;          // component 0
#pragma unroll
            for (int s = 0; s < 4; ++s) {
                float r = row_dot(W4, hr);
                hr += RDIM; if (hr >= ring_end) hr -= RINGF;
                if (act) pw[s * 320] = r;
            }
            BAR_T4_ARRIVE();                        // release consumers
            par ^= 1;
            __syncthreads();                        // B0
        }
    } else {
        // ============ OLD-TAP PRODUCERS (warps 0-7): taps {24,96,168} ======
        const bool act = tid < 240;
        const int kq   = act ? tid / 80 : 0;        // 0,1,2 -> tau 24/96/168
        const int i    = act ? tid % 80 : 0;
        const int tau  = (kq == 0) ? 24 : (kq == 1) ? 96 : 168;

        u64 Wo[40];
        load_wrow(Wo, Wfb + ((size_t)(kq + 2) * RDIM + i) * RDIM);

        // first rows computed are for steps 4..7 (superstep 1):
        // slot (4 + s - tau) mod 169
        int slot0 = ((4 - tau) % RING + RING) % RING;
        const float* hr = Hring + slot0 * RDIM;
        int par = 0;

#pragma unroll 1
        for (int n = 0; n < NSUPER; ++n) {
            float* pw = buf + (par ^ 1) * BUFBANK + i * 4 + (1 + kq);
#pragma unroll
            for (int s = 0; s < 4; ++s) {
                float r = row_dot(Wo, hr);
                hr += RDIM; if (hr >= ring_end) hr -= RINGF;
                if (act) pw[s * 320] = r;
            }
            par ^= 1;
            __syncthreads();                        // B0 publishes partials
        }
    }
}

extern "C" void kernel_launch(void* const* d_in, const int* in_sizes, int n_in,
                              void* d_out, int out_size)
{
    const float* x    = (const float*)d_in[0];  // [64, 8192, 1]
    const float* Win  = (const float*)d_in[1];  // [80, 1]
    const float* Wfb  = (const float*)d_in[2];  // [5, 80, 80]
    const float* bias = (const float*)d_in[3];  // [80]
    float* out = (float*)d_out;                 // [64, 8192, 80]

    const int smem_bytes = (RINGF + SEQ + 2 * BUFBANK) * sizeof(float);
    cudaFuncSetAttribute(reservoir_kernel,
                         cudaFuncAttributeMaxDynamicSharedMemorySize, smem_bytes);

    reservoir_kernel<<<BATCH, NTHREADS, smem_bytes>>>(x, Win, Wfb, bias, out);
}

// round 13
// speedup vs baseline: 1.3085x; 1.3085x over previous
#include <cuda_runtime.h>
#include <cstdint>

#define BATCH    64
#define SEQ      8192
#define RDIM     80
#define NTAPS    5
#define RING     256           // power-of-two ring (+8 mirror slots below)
#define NSLOT    264           // 256 + 8 mirrors of slots 0..7
#define CHUNK    8             // unrolled steps per chunk
#define NTHREADS 320           // i = tid % 80, jh = tid / 80
#define JSLICE   20
#define NPAIR    10

typedef unsigned long long u64;

__device__ __forceinline__ u64 ffma2(u64 a, u64 b, u64 c) {
    u64 d;
    asm("fma.rn.f32x2 %0, %1, %2, %3;" : "=l"(d) : "l"(a), "l"(b), "l"(c));
    return d;
}

__device__ __forceinline__ float2 unpack2(u64 v) {
    unsigned lo, hi;
    asm("mov.b64 {%0, %1}, %2;" : "=r"(lo), "=r"(hi) : "l"(v));
    float2 r; r.x = __uint_as_float(lo); r.y = __uint_as_float(hi);
    return r;
}

__device__ __forceinline__ float fast_tanh(float v) {
    v = fminf(fmaxf(v, -15.0f), 15.0f);
    float u = __expf(-2.0f * v);
    return __fdividef(1.0f - u, 1.0f + u);
}

// Accumulate one tap row (20 floats at compile-time-offset address)
#define TAP_ACC(k, ptr)                                                   \
    do {                                                                  \
        const ulonglong2* hv = reinterpret_cast<const ulonglong2*>(ptr);  \
        ulonglong2 h01 = hv[0];                                           \
        ulonglong2 h23 = hv[1];                                           \
        ulonglong2 h45 = hv[2];                                           \
        ulonglong2 h67 = hv[3];                                           \
        ulonglong2 h89 = hv[4];                                           \
        a0 = ffma2(h01.x, Wp[k][0], a0);                                  \
        a1 = ffma2(h01.y, Wp[k][1], a1);                                  \
        a2 = ffma2(h23.x, Wp[k][2], a2);                                  \
        a3 = ffma2(h23.y, Wp[k][3], a3);                                  \
        a0 = ffma2(h45.x, Wp[k][4], a0);                                  \
        a1 = ffma2(h45.y, Wp[k][5], a1);                                  \
        a2 = ffma2(h67.x, Wp[k][6], a2);                                  \
        a3 = ffma2(h67.y, Wp[k][7], a3);                                  \
        a0 = ffma2(h89.x, Wp[k][8], a0);                                  \
        a1 = ffma2(h89.y, Wp[k][9], a1);                                  \
    } while (0)

__global__ __launch_bounds__(NTHREADS, 1)
void reservoir_kernel(const float* __restrict__ x,
                      const float* __restrict__ Win,
                      const float* __restrict__ Wfb,
                      const float* __restrict__ bias,
                      float* __restrict__ out)
{
    extern __shared__ float sm[];
    float* Hring = sm;                      // [NSLOT][RDIM] = 21120 f
    float* xs    = Hring + NSLOT * RDIM;    // [SEQ]         = 8192 f
    float* part  = xs + SEQ;                // [320]           part[i*4+jh]

    const int b   = blockIdx.x;
    const int tid = threadIdx.x;
    const int i   = tid % RDIM;   // neuron index
    const int jh  = tid / RDIM;   // j-quarter 0..3

    for (int idx = tid; idx < NSLOT * RDIM; idx += NTHREADS) Hring[idx] = 0.0f;

    const float* xb = x + (size_t)b * SEQ;
    for (int idx = tid; idx < SEQ; idx += NTHREADS) xs[idx] = xb[idx];

    // feedback[i] = sum_k sum_j delayed[k][j] * Wfb[k][i][j]
    u64 Wp[NTAPS][NPAIR];
#pragma unroll
    for (int k = 0; k < NTAPS; k++) {
        const float* wrow = Wfb + ((size_t)k * RDIM + i) * RDIM + jh * JSLICE;
#pragma unroll
        for (int p = 0; p < NPAIR; p++) {
            unsigned lo = __float_as_uint(wrow[2 * p]);
            unsigned hi = __float_as_uint(wrow[2 * p + 1]);
            Wp[k][p] = ((u64)hi << 32) | (u64)lo;
        }
    }

    float win_i = 0.0f, bias_i = 0.0f, h_i = 0.0f;
    if (tid < RDIM) { win_i = Win[tid]; bias_i = bias[tid]; }

    float* outb = out + (size_t)b * SEQ * RDIM;

    __syncthreads();

#pragma unroll 1
    for (int T = 0; T < SEQ; T += CHUNK) {
        // Per-chunk base pointers (the ONLY ring arithmetic; all per-step
        // addresses below are base + compile-time immediate offsets).
        // Slots: tap tau reads (T + s - tau) & 255 = b_tau + s, where
        // b_tau = (T - tau) & 255. taus {24,96,168} are 0 mod 8 so
        // b + 7 <= 255 always; taus {1,4} may run into mirror slots
        // 256..262 which duplicate slots 0..6 (written below).
        const float* p1   = Hring + ((unsigned)(T - 1)   & 255u) * RDIM + jh * JSLICE;
        const float* p4   = Hring + ((unsigned)(T - 4)   & 255u) * RDIM + jh * JSLICE;
        const float* p24  = Hring + ((unsigned)(T - 24)  & 255u) * RDIM + jh * JSLICE;
        const float* p96  = Hring + ((unsigned)(T - 96)  & 255u) * RDIM + jh * JSLICE;
        const float* p168 = Hring + ((unsigned)(T - 168) & 255u) * RDIM + jh * JSLICE;
        const int   W0    = T & 255;                 // write slot of step T
        float*      hwr   = Hring + W0 * RDIM + i;   // epilogue h write base
        const bool  mirror = (W0 == 0);              // this chunk writes slots 0..7
        float*      op    = outb + (size_t)T * RDIM + i;
        const float* xp   = xs + T;

#pragma unroll
        for (int s = 0; s < CHUNK; ++s) {
            u64 a0 = 0ull, a1 = 0ull, a2 = 0ull, a3 = 0ull;

            // ---- P1: old taps {4,24,96,168} (need h[t-4] and older;
            // visible since BAR A of step t-3). Immediate-offset LDS.
            TAP_ACC(1, p4   + s * RDIM);
            TAP_ACC(2, p24  + s * RDIM);
            TAP_ACC(3, p96  + s * RDIM);
            TAP_ACC(4, p168 + s * RDIM);

            // ---- BAR A: h[t-1] (epilogue of t-1) visible.
            __syncthreads();

            // ---- P2: tau=1 (needs h[t-1])
            TAP_ACC(0, p1 + s * RDIM);

            float2 f0 = unpack2(a0);
            float2 f1 = unpack2(a1);
            float2 f2 = unpack2(a2);
            float2 f3 = unpack2(a3);
            part[i * 4 + jh] =
                ((f0.x + f0.y) + (f1.x + f1.y)) + ((f2.x + f2.y) + (f3.x + f3.y));

            // ---- BAR B: partials visible.
            __syncthreads();

            // ---- Epilogue (80 threads): reduce + tanh + publish.
            // Single part buffer is safe: next write (P2 of t+1) happens
            // only after BAR A(t+1), which this thread gates.
            if (tid < RDIM) {
                float4 p4v = *reinterpret_cast<const float4*>(part + 4 * tid);
                float f = (p4v.x + p4v.y) + (p4v.z + p4v.w);
                float val = fmaf(xp[s], win_i, f + bias_i);
                h_i = 0.7f * h_i + 0.3f * fast_tanh(val);
                hwr[s * RDIM] = h_i;                       // slot W0+s
                if (mirror)
                    hwr[(256 + s) * RDIM] = h_i;           // mirror 256..263
                op[(size_t)s * RDIM] = h_i;
            }
        }
    }
}

extern "C" void kernel_launch(void* const* d_in, const int* in_sizes, int n_in,
                              void* d_out, int out_size)
{
    const float* x    = (const float*)d_in[0];  // [64, 8192, 1]
    const float* Win  = (const float*)d_in[1];  // [80, 1]
    const float* Wfb  = (const float*)d_in[2];  // [5, 80, 80]
    const float* bias = (const float*)d_in[3];  // [80]
    float* out = (float*)d_out;                 // [64, 8192, 80]

    const int smem_bytes = (NSLOT * RDIM + SEQ + NTHREADS) * sizeof(float);
    cudaFuncSetAttribute(reservoir_kernel,
                         cudaFuncAttributeMaxDynamicSharedMemorySize, smem_bytes);

    reservoir_kernel<<<BATCH, NTHREADS, smem_bytes>>>(x, Win, Wfb, bias, out);
}